// round 17
// baseline (speedup 1.0000x reference)
#include <cuda_runtime.h>
#include <math.h>

#define THREADS 256
#define NPTS 4096
#define BATCH 2
#define BN (BATCH * NPTS)        // 8192 queries per side
#define INV_TAU 50.0f
#define NKEXP (-72.13475204444817f)  // -1/(TAU*ln2)
#define INV_NK (-0.013862943611198906f)   // 1/NKEXP
#define COEF (1.0f / (float)(BATCH * NPTS))
#define PW_BLOCKS 448

// fused stats: 4 queries/lane, 64 opponents/block
#define SF_QPL 4
#define SF_QPB (THREADS * SF_QPL)      // 1024 queries per block
#define SF_OPB 64                      // opponents per block
// grad: 2 queries/lane, 128 opponents/block
#define G_QPL 2
#define G_QPB (THREADS * G_QPL)        // 512 queries per block
#define G_OPB 128

// ---- scalar HW approximations ----
__device__ __forceinline__ float ex2(float x) {
    float y; asm("ex2.approx.ftz.f32 %0, %1;" : "=f"(y) : "f"(x)); return y;
}
__device__ __forceinline__ float rsq(float x) {
    float y; asm("rsqrt.approx.f32 %0, %1;" : "=f"(y) : "f"(x)); return y;
}
__device__ __forceinline__ float sqa(float x) {
    float y; asm("sqrt.approx.ftz.f32 %0, %1;" : "=f"(y) : "f"(x)); return y;
}
__device__ __forceinline__ float rcp(float x) {
    float y; asm("rcp.approx.ftz.f32 %0, %1;" : "=f"(y) : "f"(x)); return y;
}

// ---- accumulator state ----
__device__ float g_pw[4][PW_BLOCKS];
__device__ float g_Zacc[2][BN];       // [0]=col(target), [1]=row(pred) — atomic-add
__device__ float g_Suacc[2][BN];      // sum p*arg (arg = d*NKEXP)
__device__ unsigned g_mnacc[2][BN];   // min d2 bits
__device__ __align__(16) float2 g_stats[2][BN];   // (COEF/Z, 1+T/tau)
__device__ float g_gacc[3][BN];       // grad components — atomic-add
__device__ float g_sf_mn[64];
__device__ float g_sf_T[64];
__device__ float g_gf[32];

__device__ __forceinline__ float warpSum(float v) {
#pragma unroll
    for (int o = 16; o > 0; o >>= 1) v += __shfl_xor_sync(0xffffffffu, v, o);
    return v;
}
__device__ __forceinline__ float blockSum(float v, float* sh) {
    __syncthreads();
    v = warpSum(v);
    int w = threadIdx.x >> 5, l = threadIdx.x & 31;
    if (l == 0) sh[w] = v;
    __syncthreads();
    if (threadIdx.x == 0) {
        float x = 0.f;
#pragma unroll
        for (int i = 0; i < THREADS / 32; i++) x += sh[i];
        sh[0] = x;
    }
    __syncthreads();
    return sh[0];
}

// ---------------- zero atomic targets (8192 threads) ----------------
__global__ void zero_kernel() {
    int i = blockIdx.x * blockDim.x + threadIdx.x;   // 0..8191
    g_Zacc[0][i] = 0.f;  g_Zacc[1][i] = 0.f;
    g_Suacc[0][i] = 0.f; g_Suacc[1][i] = 0.f;
    g_mnacc[0][i] = 0x7F800000u; g_mnacc[1][i] = 0x7F800000u;
    g_gacc[0][i] = 0.f; g_gacc[1][i] = 0.f; g_gacc[2][i] = 0.f;
}

// ---------------- pointwise losses over B*P points ----------------
__global__ void pointwise_kernel(const float* __restrict__ sp, const float* __restrict__ st,
                                 const float* __restrict__ un, const float* __restrict__ op,
                                 const float* __restrict__ ot, const float* __restrict__ na_,
                                 const float* __restrict__ nb_, int n) {
    float s_l1 = 0.f, s_bce = 0.f, s_unc = 0.f, s_nrm = 0.f;
    for (int i = blockIdx.x * blockDim.x + threadIdx.x; i < n; i += gridDim.x * blockDim.x) {
        s_l1 += fabsf(sp[i] - st[i]);
        float p = op[i], t = ot[i];
        s_bce -= t * __logf(p) + (1.f - t) * __logf(1.f - p);
        float u = un[i];
        s_unc += u * (1.f - u);
        float ax = na_[3 * i], ay = na_[3 * i + 1], az = na_[3 * i + 2];
        float bx = nb_[3 * i], by = nb_[3 * i + 1], bz = nb_[3 * i + 2];
        float nna2 = fmaf(ax, ax, fmaf(ay, ay, az * az));
        float nnb2 = fmaf(bx, bx, fmaf(by, by, bz * bz));
        float inv = rsq(fmaxf(nna2, 1e-16f)) * rsq(fmaxf(nnb2, 1e-16f));
        float cs = fmaf(ax, bx, fmaf(ay, by, az * bz)) * inv;
        s_nrm += 1.f - cs;
    }
    __shared__ float sh[8];
    float v;
    v = blockSum(s_l1, sh);  if (threadIdx.x == 0) g_pw[0][blockIdx.x] = v;
    v = blockSum(s_bce, sh); if (threadIdx.x == 0) g_pw[1][blockIdx.x] = v;
    v = blockSum(s_unc, sh); if (threadIdx.x == 0) g_pw[2][blockIdx.x] = v;
    v = blockSum(s_nrm, sh); if (threadIdx.x == 0) g_pw[3][blockIdx.x] = v;
}

// -------- fused stats: ONE sweep of d(n,m) produces BOTH row & col softmax stats --------
// queries = preds (4 per lane, register-resident); opponents = targets (broadcast from smem)
// grid: (4096/SF_QPB)=4  x BATCH  x (4096/SF_OPB)=64   => 512 blocks
__global__ void stats_kernel(const float* __restrict__ prd, const float* __restrict__ tgt) {
    __shared__ float sox[SF_OPB], soy[SF_OPB], soz[SF_OPB];
    int t = threadIdx.x;
    int b = blockIdx.y;
    int obase = blockIdx.z * SF_OPB;

    for (int j = t; j < 3 * SF_OPB; j += THREADS) {
        int o = j / 3, c = j - 3 * o;
        float v = tgt[((size_t)b * NPTS + obase) * 3 + j];
        (c == 0 ? sox : c == 1 ? soy : soz)[o] = v;
    }

    // load 4 queries per lane
    float qx[SF_QPL], qy[SF_QPL], qz[SF_QPL];
    float Zr[SF_QPL], Sur[SF_QPL], mnr[SF_QPL];
    int q0 = blockIdx.x * SF_QPB + t;
#pragma unroll
    for (int k = 0; k < SF_QPL; k++) {
        const float* q = prd + ((size_t)b * NPTS + q0 + k * THREADS) * 3;
        qx[k] = q[0]; qy[k] = q[1]; qz[k] = q[2];
        Zr[k] = 0.f; Sur[k] = 0.f; mnr[k] = 1e30f;
    }
    __syncthreads();

#pragma unroll 2
    for (int o = 0; o < SF_OPB; o++) {
        float ox = sox[o], oy = soy[o], oz = soz[o];
        float pc = 0.f, pca = 0.f, mo2 = 1e30f;   // col partials for this opponent
#pragma unroll
        for (int k = 0; k < SF_QPL; k++) {
            float dx = qx[k] - ox, dy = qy[k] - oy, dz = qz[k] - oz;
            float d2 = fmaxf(fmaf(dx, dx, fmaf(dy, dy, dz * dz)), 1e-12f);
            mnr[k] = fminf(mnr[k], d2);
            mo2 = fminf(mo2, d2);
            float arg = sqa(d2) * NKEXP;
            float p = ex2(arg);
            Zr[k] += p;
            Sur[k] = fmaf(p, arg, Sur[k]);
            pc += p;
            pca = fmaf(p, arg, pca);
        }
        // warp butterfly: combine col partials across 32 lanes
#pragma unroll
        for (int s = 16; s > 0; s >>= 1) {
            pc += __shfl_xor_sync(0xffffffffu, pc, s);
            pca += __shfl_xor_sync(0xffffffffu, pca, s);
            mo2 = fminf(mo2, __shfl_xor_sync(0xffffffffu, mo2, s));
        }
        if ((t & 31) == 0) {
            int cidx = b * NPTS + obase + o;
            atomicAdd(&g_Zacc[0][cidx], pc);
            atomicAdd(&g_Suacc[0][cidx], pca);
            atomicMin(&g_mnacc[0][cidx], __float_as_uint(mo2));
        }
    }
    // row partials
#pragma unroll
    for (int k = 0; k < SF_QPL; k++) {
        int ridx = b * NPTS + q0 + k * THREADS;
        atomicAdd(&g_Zacc[1][ridx], Zr[k]);
        atomicAdd(&g_Suacc[1][ridx], Sur[k]);
        atomicMin(&g_mnacc[1][ridx], __float_as_uint(mnr[k]));
    }
}

// -------- finalize stats: 16384 queries --------
__global__ void stats_fin_kernel() {
    int i = blockIdx.x * blockDim.x + threadIdx.x;   // 0..16383
    int side = i >> 13;
    int q = i & (BN - 1);
    float Z = g_Zacc[side][q];
    float Su = g_Suacc[side][q];
    float rz = rcp(Z);
    float T = Su * rz * INV_NK;
    g_stats[side][q] = make_float2(COEF * rz, fmaf(T, INV_TAU, 1.f));
    float mn = sqrtf(__uint_as_float(g_mnacc[side][q]));
    __shared__ float sh[8];
    float mnS = blockSum(mn, sh);
    float TS = blockSum(T, sh);
    if (threadIdx.x == 0) {
        g_sf_mn[blockIdx.x] = mnS;
        g_sf_T[blockIdx.x] = TS;
    }
}

// -------- grad: query-per-lane, broadcast opponents + col stats --------
// grid: (4096/G_QPB)=8  x BATCH  x (4096/G_OPB)=32   => 512 blocks
__global__ void grad_kernel(const float* __restrict__ prd, const float* __restrict__ tgt) {
    __shared__ float sox[G_OPB], soy[G_OPB], soz[G_OPB], scx[G_OPB], scy[G_OPB];
    int t = threadIdx.x;
    int b = blockIdx.y;
    int obase = blockIdx.z * G_OPB;

    for (int j = t; j < 3 * G_OPB; j += THREADS) {   // FIX: strided (384 > 256)
        int o = j / 3, c = j - 3 * o;
        float v = tgt[((size_t)b * NPTS + obase) * 3 + j];
        (c == 0 ? sox : c == 1 ? soy : soz)[o] = v;
    }
    if (t < G_OPB) {
        float2 cs = g_stats[0][b * NPTS + obase + t];
        scx[t] = cs.x; scy[t] = cs.y;
    }

    float qx[G_QPL], qy[G_QPL], qz[G_QPL];
    float A0[G_QPL], nB0[G_QPL];
    float gx[G_QPL], gy[G_QPL], gz[G_QPL];
    int q0 = blockIdx.x * G_QPB + t;
#pragma unroll
    for (int k = 0; k < G_QPL; k++) {
        int n = q0 + k * THREADS;
        const float* q = prd + ((size_t)b * NPTS + n) * 3;
        qx[k] = q[0]; qy[k] = q[1]; qz[k] = q[2];
        float2 rs = g_stats[1][b * NPTS + n];
        A0[k] = rs.x * rs.y;
        nB0[k] = -rs.x * INV_TAU;
        gx[k] = 0.f; gy[k] = 0.f; gz[k] = 0.f;
    }
    __syncthreads();

#pragma unroll 2
    for (int o = 0; o < G_OPB; o++) {
        float ox = sox[o], oy = soy[o], oz = soz[o];
        float csx = scx[o], csy = scy[o];
#pragma unroll
        for (int k = 0; k < G_QPL; k++) {
            float dx = qx[k] - ox, dy = qy[k] - oy, dz = qz[k] - oz;
            float d2 = fmaxf(fmaf(dx, dx, fmaf(dy, dy, dz * dz)), 1e-12f);
            float r = rsq(d2);
            float p = ex2((d2 * NKEXP) * r);
            float t1 = fmaf(csx, csy, A0[k]);
            float nt2 = fmaf(csx, -INV_TAU, nB0[k]);
            float w = p * fmaf(t1, r, nt2);
            gx[k] = fmaf(w, dx, gx[k]);
            gy[k] = fmaf(w, dy, gy[k]);
            gz[k] = fmaf(w, dz, gz[k]);
        }
    }
#pragma unroll
    for (int k = 0; k < G_QPL; k++) {
        int idx = b * NPTS + q0 + k * THREADS;
        atomicAdd(&g_gacc[0][idx], gx[k]);
        atomicAdd(&g_gacc[1][idx], gy[k]);
        atomicAdd(&g_gacc[2][idx], gz[k]);
    }
}

// -------- finalize grad: 8192 queries --------
__global__ void grad_fin_kernel() {
    int i = blockIdx.x * blockDim.x + threadIdx.x;
    float gx = g_gacc[0][i], gy = g_gacc[1][i], gz = g_gacc[2][i];
    float nrm = sqrtf(fmaf(gx, gx, fmaf(gy, gy, gz * gz)));
    __shared__ float sh[8];
    float vs = blockSum(fabsf(nrm - 1.f), sh);
    if (threadIdx.x == 0) g_gf[blockIdx.x] = vs;
}

// ---------------- final: gather all partials ----------------
__global__ void final_kernel(float* __restrict__ out, int bp) {
    int t = threadIdx.x;
    float s0 = 0.f, s1 = 0.f, s2 = 0.f, s3 = 0.f, sMn = 0.f, sT = 0.f, sG = 0.f;
    for (int i = t; i < PW_BLOCKS; i += THREADS) {
        s0 += g_pw[0][i]; s1 += g_pw[1][i]; s2 += g_pw[2][i]; s3 += g_pw[3][i];
    }
    if (t < 64) { sMn = g_sf_mn[t]; sT = g_sf_T[t]; }
    if (t < 32) sG = g_gf[t];
    __shared__ float sh[8];
    s0 = blockSum(s0, sh);
    s1 = blockSum(s1, sh);
    s2 = blockSum(s2, sh);
    s3 = blockSum(s3, sh);
    sMn = blockSum(sMn, sh);
    sT = blockSum(sT, sh);
    sG = blockSum(sG, sh);
    if (t == 0) {
        float invBP = 1.f / (float)bp;
        float invBN = 1.f / (float)BN;
        float l1 = s0 * invBP;
        float bce = s1 * invBP;
        float unc = s2 * invBP;
        float nrm = s3 * invBP;
        float cham = sMn * invBN;
        float emd = sT * invBN;
        float gp = sG * invBN;
        float pt = expf(-bce);
        float occ = 0.75f * (1.f - pt) * (1.f - pt) * bce;
        out[0] = l1 + occ + 0.1f * nrm + cham + 0.25f * emd + 0.05f * gp + 0.1f * unc;
    }
}

extern "C" void kernel_launch(void* const* d_in, const int* in_sizes, int n_in,
                              void* d_out, int out_size) {
    const float* sdf_pred   = (const float*)d_in[0];
    const float* sdf_target = (const float*)d_in[1];
    const float* uncertainty = (const float*)d_in[2];
    const float* occ_pred   = (const float*)d_in[3];
    const float* occ_target = (const float*)d_in[4];
    const float* nrm_pred   = (const float*)d_in[5];
    const float* nrm_target = (const float*)d_in[6];
    const float* pc_pred    = (const float*)d_in[7];
    const float* pc_target  = (const float*)d_in[8];
    float* out = (float*)d_out;

    int bp = in_sizes[0];   // B * P = 200000

    zero_kernel<<<BN / THREADS, THREADS>>>();
    pointwise_kernel<<<PW_BLOCKS, THREADS>>>(sdf_pred, sdf_target, uncertainty,
                                             occ_pred, occ_target, nrm_pred, nrm_target, bp);
    dim3 sgrid(NPTS / SF_QPB, BATCH, NPTS / SF_OPB);   // 4 x 2 x 64 = 512
    stats_kernel<<<sgrid, THREADS>>>(pc_pred, pc_target);
    stats_fin_kernel<<<64, THREADS>>>();
    dim3 ggrid(NPTS / G_QPB, BATCH, NPTS / G_OPB);     // 8 x 2 x 32 = 512
    grad_kernel<<<ggrid, THREADS>>>(pc_pred, pc_target);
    grad_fin_kernel<<<32, THREADS>>>();
    final_kernel<<<1, THREADS>>>(out, bp);
}